// round 9
// baseline (speedup 1.0000x reference)
#include <cuda_runtime.h>
#include <cstdint>

#define N_NODES 100000
#define D       128
#define R       4
#define E       500000
#define RN      (R * N_NODES)
#define REDGES  (R * E)
#define NB      782
#define NTILE   782

// ---------------- scratch (static device globals; no runtime allocs) ----------
__device__ float g_neigh[(size_t)R * N_NODES * D];   // mean-aggregated neighbors
__device__ int   g_cnti[RN];
__device__ int   g_off[RN];      // block-local exclusive; fill bumps to local END
__device__ int   g_bsum[1024];
__device__ int   g_bscan[1024];  // exclusive scan of 512-chunk block sums
__device__ int   g_esrc[REDGES];
__device__ float g_Wt[(R + 1) * D * D];   // [seg][k][n], scaled
__device__ float g_bavg[D];

// =================== helpers ====================================================
__device__ __forceinline__ uint32_t f2tf32(float f) {
    uint32_t u;
    asm("cvt.rna.tf32.f32 %0, %1;" : "=r"(u) : "f"(f));
    return u;
}
__device__ __forceinline__ void mma8(float* c, const uint32_t* a, const uint32_t* b) {
    asm volatile(
        "mma.sync.aligned.m16n8k8.row.col.f32.tf32.tf32.f32 "
        "{%0,%1,%2,%3}, {%4,%5,%6,%7}, {%8,%9}, {%0,%1,%2,%3};"
        : "+f"(c[0]), "+f"(c[1]), "+f"(c[2]), "+f"(c[3])
        : "r"(a[0]), "r"(a[1]), "r"(a[2]), "r"(a[3]), "r"(b[0]), "r"(b[1]));
}
__device__ __forceinline__ uint32_t smem_u32(const void* p) {
    uint32_t a;
    asm("{ .reg .u64 t; cvta.to.shared.u64 t, %1; cvt.u32.u64 %0, t; }" : "=r"(a) : "l"(p));
    return a;
}
__device__ __forceinline__ void cp16(uint32_t dst, const void* src, bool ok) {
    int sz = ok ? 16 : 0;
    asm volatile("cp.async.cg.shared.global [%0], [%1], 16, %2;"
                 :: "r"(dst), "l"(src), "r"(sz) : "memory");
}
#define CP_COMMIT() asm volatile("cp.async.commit_group;" ::: "memory")
#define CP_WAIT(n)  asm volatile("cp.async.wait_group %0;" :: "n"(n) : "memory")

// ---------------- weight precombine: g_Wt[seg][k][n] ---------------------------
__global__ __launch_bounds__(256) void combine_kernel(const float* __restrict__ Ws,
                                                      const float* __restrict__ Wn,
                                                      const float* __restrict__ b) {
    int i = blockIdx.x * blockDim.x + threadIdx.x;
    if (i < (R + 1) * D * D) {
        int seg = i >> 14, rem = i & 16383;
        float v;
        if (seg == 0) {
            v = 0.f;
            #pragma unroll
            for (int r = 0; r < R; r++) v += Ws[r * D * D + rem];
            v *= 0.25f;
        } else {
            v = Wn[(seg - 1) * D * D + rem] * 0.25f;
        }
        g_Wt[i] = v;
    }
    if (i < D) {
        float s = 0.f;
        #pragma unroll
        for (int r = 0; r < R; r++) s += b[r * D + i];
        g_bavg[i] = s * 0.25f;
    }
}

// ---------------- CSR build ----------------------------------------------------
__global__ __launch_bounds__(256) void zero_kernel() {
    int i = blockIdx.x * blockDim.x + threadIdx.x;
    if (i < RN) g_cnti[i] = 0;
}
__global__ __launch_bounds__(256) void count_kernel(const int* __restrict__ dst) {
    int i = blockIdx.x * blockDim.x + threadIdx.x;
    if (i >= REDGES) return;
    int r = i / E;
    atomicAdd(&g_cnti[r * N_NODES + dst[i]], 1);
}
__global__ __launch_bounds__(512) void scan1_kernel() {
    __shared__ int tmp[512];
    int t = threadIdx.x, i = blockIdx.x * 512 + t;
    int v = (i < RN) ? g_cnti[i] : 0;
    tmp[t] = v;
    __syncthreads();
    for (int o = 1; o < 512; o <<= 1) {
        int a = (t >= o) ? tmp[t - o] : 0;
        __syncthreads();
        tmp[t] += a;
        __syncthreads();
    }
    if (i < RN) g_off[i] = tmp[t] - v;
    if (t == 511) g_bsum[blockIdx.x] = tmp[511];
}
__global__ __launch_bounds__(1024) void scan2_kernel() {
    __shared__ int tmp[1024];
    int t = threadIdx.x;
    int v = (t < NB) ? g_bsum[t] : 0;
    tmp[t] = v;
    __syncthreads();
    for (int o = 1; o < 1024; o <<= 1) {
        int a = (t >= o) ? tmp[t - o] : 0;
        __syncthreads();
        tmp[t] += a;
        __syncthreads();
    }
    if (t < NB) g_bscan[t] = tmp[t] - v;
}
// global position = block-local offset + g_bscan[rd>>9]; fill bumps g_off
__global__ __launch_bounds__(256) void fill_kernel(const int* __restrict__ src,
                                                   const int* __restrict__ dst) {
    int i = blockIdx.x * blockDim.x + threadIdx.x;
    if (i >= REDGES) return;
    int r = i / E;
    int rd = r * N_NODES + dst[i];
    int pos = atomicAdd(&g_off[rd], 1) + g_bscan[rd >> 9];
    g_esrc[pos] = src[i];
}

// ---------------- aggregate: one warp per (relation,node) ----------------------
__global__ __launch_bounds__(256) void aggregate_kernel(const float* __restrict__ x) {
    int gw = (int)(((size_t)blockIdx.x * blockDim.x + threadIdx.x) >> 5);
    int lane = threadIdx.x & 31;
    if (gw >= RN) return;

    int cdeg = g_cnti[gw];
    int base = g_off[gw] + g_bscan[gw >> 9] - cdeg;   // local end + block base - cnt

    float4 s0 = make_float4(0.f, 0.f, 0.f, 0.f);
    float4 s1 = make_float4(0.f, 0.f, 0.f, 0.f);
    float4 s2 = make_float4(0.f, 0.f, 0.f, 0.f);
    float4 s3 = make_float4(0.f, 0.f, 0.f, 0.f);
    int e = 0;
    for (; e + 4 <= cdeg; e += 4) {
        int sa = g_esrc[base + e];
        int sb = g_esrc[base + e + 1];
        int sc = g_esrc[base + e + 2];
        int sd = g_esrc[base + e + 3];
        float4 va = *(const float4*)(x + (size_t)sa * D + lane * 4);
        float4 vb = *(const float4*)(x + (size_t)sb * D + lane * 4);
        float4 vc = *(const float4*)(x + (size_t)sc * D + lane * 4);
        float4 vd = *(const float4*)(x + (size_t)sd * D + lane * 4);
        s0.x += va.x; s0.y += va.y; s0.z += va.z; s0.w += va.w;
        s1.x += vb.x; s1.y += vb.y; s1.z += vb.z; s1.w += vb.w;
        s2.x += vc.x; s2.y += vc.y; s2.z += vc.z; s2.w += vc.w;
        s3.x += vd.x; s3.y += vd.y; s3.z += vd.z; s3.w += vd.w;
    }
    for (; e < cdeg; e++) {
        int sa = g_esrc[base + e];
        float4 va = *(const float4*)(x + (size_t)sa * D + lane * 4);
        s0.x += va.x; s0.y += va.y; s0.z += va.z; s0.w += va.w;
    }
    float ic = 1.f / fmaxf((float)cdeg, 1.f);
    float4 o;
    o.x = (s0.x + s1.x + s2.x + s3.x) * ic;
    o.y = (s0.y + s1.y + s2.y + s3.y) * ic;
    o.z = (s0.z + s1.z + s2.z + s3.z) * ic;
    o.w = (s0.w + s1.w + s2.w + s3.w) * ic;
    *(float4*)(g_neigh + (size_t)gw * D + lane * 4) = o;
}

// ---------------- tf32 GEMM with cp.async 3-stage pipeline ---------------------
// 256 threads, tile 128x128, warp tile 64x32 (8 warps 2x4). 20 chunks
// (5 segs x 4 k-chunks of 32). NO occupancy clause -> no register spills.
#define A_BYTES 18432
#define STAGE_B 35328
#define SM_GEMM (3 * STAGE_B)    // 105984

__global__ __launch_bounds__(256) void gemm_kernel(const float* __restrict__ x,
                                                   float* __restrict__ out) {
    extern __shared__ char smem[];
    uint32_t sbase = smem_u32(smem);

    int tid  = threadIdx.x;
    int wid  = tid >> 5, lane = tid & 31;
    int qid  = lane >> 2, kid = lane & 3;
    int wm   = wid & 1, wn = wid >> 1;
    int row0 = blockIdx.x * 128;

    float c[4][4][4];
    #pragma unroll
    for (int mt = 0; mt < 4; mt++)
        #pragma unroll
        for (int nt = 0; nt < 4; nt++)
            #pragma unroll
            for (int j = 0; j < 4; j++) c[mt][nt][j] = 0.f;

    int rowA = tid >> 1, fA = (tid & 1) * 4;
    int kkB  = tid >> 3, fB = (tid & 7) * 4;

    auto issue_chunk = [&](int ch, int st) {
        int seg = ch >> 2, k0 = (ch & 3) * 32;
        const float* Abase = (seg == 0) ? x
                           : (g_neigh + (size_t)(seg - 1) * N_NODES * D);
        int n = row0 + rowA;
        bool ok = (n < N_NODES);
        const float* asrc = Abase + (size_t)(ok ? n : 0) * D + k0 + fA * 4;
        uint32_t adst = sbase + st * STAGE_B + rowA * 144 + fA * 16;
        #pragma unroll
        for (int p = 0; p < 4; p++)
            cp16(adst + p * 16, asrc + p * 4, ok);

        const float* bsrc = g_Wt + seg * D * D + (size_t)(k0 + kkB) * D + fB * 4;
        uint32_t bdst = sbase + st * STAGE_B + A_BYTES + kkB * 528 + fB * 16;
        #pragma unroll
        for (int p = 0; p < 4; p++)
            cp16(bdst + p * 16, bsrc + p * 4, true);
        CP_COMMIT();
    };

    issue_chunk(0, 0);
    issue_chunk(1, 1);
    issue_chunk(2, 2);

    #pragma unroll 1
    for (int ch = 0; ch < 20; ch++) {
        int st = ch % 3;
        if (ch == 18)      CP_WAIT(1);
        else if (ch == 19) CP_WAIT(0);
        else               CP_WAIT(2);
        __syncthreads();

        const float* As = (const float*)(smem + st * STAGE_B);            // [128][36]
        const float* Bs = (const float*)(smem + st * STAGE_B + A_BYTES);  // [32][132]

        #pragma unroll
        for (int kk8 = 0; kk8 < 4; kk8++) {
            int k8 = kk8 * 8;
            uint32_t a[4][4], b[4][2];
            #pragma unroll
            for (int mt = 0; mt < 4; mt++) {
                int row = wm * 64 + mt * 16 + qid;
                a[mt][0] = f2tf32(As[row * 36 + k8 + kid]);
                a[mt][1] = f2tf32(As[(row + 8) * 36 + k8 + kid]);
                a[mt][2] = f2tf32(As[row * 36 + k8 + 4 + kid]);
                a[mt][3] = f2tf32(As[(row + 8) * 36 + k8 + 4 + kid]);
            }
            #pragma unroll
            for (int nt = 0; nt < 4; nt++) {
                int col = wn * 32 + nt * 8 + qid;
                b[nt][0] = f2tf32(Bs[(k8 + kid) * 132 + col]);
                b[nt][1] = f2tf32(Bs[(k8 + 4 + kid) * 132 + col]);
            }
            #pragma unroll
            for (int mt = 0; mt < 4; mt++)
                #pragma unroll
                for (int nt = 0; nt < 4; nt++)
                    mma8(c[mt][nt], a[mt], b[nt]);
        }

        __syncthreads();
        if (ch + 3 < 20) issue_chunk(ch + 3, st);
    }

    // ---- epilogue: add mean bias, store float2 pairs ----
    #pragma unroll
    for (int mt = 0; mt < 4; mt++) {
        int r0q = row0 + wm * 64 + mt * 16 + qid;
        #pragma unroll
        for (int nt = 0; nt < 4; nt++) {
            int col = wn * 32 + nt * 8 + kid * 2;
            float b0 = g_bavg[col], b1 = g_bavg[col + 1];
            if (r0q < N_NODES) {
                float2 o = make_float2(c[mt][nt][0] + b0, c[mt][nt][1] + b1);
                *(float2*)(out + (size_t)r0q * D + col) = o;
            }
            if (r0q + 8 < N_NODES) {
                float2 o = make_float2(c[mt][nt][2] + b0, c[mt][nt][3] + b1);
                *(float2*)(out + (size_t)(r0q + 8) * D + col) = o;
            }
        }
    }
}

// ---------------- launch --------------------------------------------------------
// Launch order puts aggregate_kernel at index 5 so ncu (-s 5 -c 1) profiles it.
extern "C" void kernel_launch(void* const* d_in, const int* in_sizes, int n_in,
                              void* d_out, int out_size) {
    const float* x      = (const float*)d_in[0];
    const int*   src    = (const int*)d_in[1];
    const int*   dst    = (const int*)d_in[2];
    const float* Wself  = (const float*)d_in[3];
    const float* Wneigh = (const float*)d_in[4];
    const float* b      = (const float*)d_in[5];
    float* out = (float*)d_out;

    zero_kernel<<<(RN + 255) / 256, 256>>>();                     // 0
    count_kernel<<<(REDGES + 255) / 256, 256>>>(dst);             // 1
    scan1_kernel<<<NB, 512>>>();                                  // 2
    scan2_kernel<<<1, 1024>>>();                                  // 3
    fill_kernel<<<(REDGES + 255) / 256, 256>>>(src, dst);         // 4
    aggregate_kernel<<<(RN * 32 + 255) / 256, 256>>>(x);          // 5 <- profiled
    combine_kernel<<<((R + 1) * D * D + 255) / 256, 256>>>(Wself, Wneigh, b);  // 6

    cudaFuncSetAttribute(gemm_kernel, cudaFuncAttributeMaxDynamicSharedMemorySize, SM_GEMM);
    gemm_kernel<<<NTILE, 256, SM_GEMM>>>(x, out);                 // 7
    (void)in_sizes; (void)n_in; (void)out_size;
}

// round 11
// speedup vs baseline: 1.3154x; 1.3154x over previous
#include <cuda_runtime.h>
#include <cstdint>

#define N_NODES 100000
#define D       128
#define R       4
#define E       500000
#define RN      (R * N_NODES)   // 400000
#define REDGES  (R * E)         // 2000000
#define NB      782             // scan blocks (512 each)
#define NTILE   782             // ceil(N_NODES/128)

// ---------------- scratch (static device globals; no runtime allocs) ----------
__device__ float g_neigh[(size_t)R * N_NODES * D];   // mean-aggregated neighbors
__device__ int   g_cnti[RN];
__device__ int   g_off[RN];      // local exclusive within 512-chunk; fill bumps
__device__ int   g_bsum[1024];
__device__ int   g_bscan[1024];  // exclusive scan of 512-chunk sums
__device__ int   g_esrc[REDGES];
__device__ float g_Wt[(R + 1) * D * D];   // [seg][k][n], scaled
__device__ float g_bavg[D];
__device__ int   g_scan_ctr;

// =================== helpers ====================================================
__device__ __forceinline__ uint32_t f2tf32(float f) {
    uint32_t u;
    asm("cvt.rna.tf32.f32 %0, %1;" : "=r"(u) : "f"(f));
    return u;
}
__device__ __forceinline__ void mma8(float* c, const uint32_t* a, const uint32_t* b) {
    asm volatile(
        "mma.sync.aligned.m16n8k8.row.col.f32.tf32.tf32.f32 "
        "{%0,%1,%2,%3}, {%4,%5,%6,%7}, {%8,%9}, {%0,%1,%2,%3};"
        : "+f"(c[0]), "+f"(c[1]), "+f"(c[2]), "+f"(c[3])
        : "r"(a[0]), "r"(a[1]), "r"(a[2]), "r"(a[3]), "r"(b[0]), "r"(b[1]));
}

// ---------------- zero counts + combine weights + reset scan counter -----------
__global__ __launch_bounds__(256) void zc_kernel(const float* __restrict__ Ws,
                                                 const float* __restrict__ Wn,
                                                 const float* __restrict__ b) {
    int i = blockIdx.x * blockDim.x + threadIdx.x;
    if (i == 0) g_scan_ctr = 0;
    if (i < RN) g_cnti[i] = 0;
    if (i < (R + 1) * D * D) {
        int seg = i >> 14, rem = i & 16383;
        float v;
        if (seg == 0) {
            v = 0.f;
            #pragma unroll
            for (int r = 0; r < R; r++) v += Ws[r * D * D + rem];
            v *= 0.25f;
        } else {
            v = Wn[(seg - 1) * D * D + rem] * 0.25f;
        }
        g_Wt[i] = v;
    }
    if (i < D) {
        float s = 0.f;
        #pragma unroll
        for (int r = 0; r < R; r++) s += b[r * D + i];
        g_bavg[i] = s * 0.25f;
    }
}

// ---------------- CSR build ----------------------------------------------------
__global__ __launch_bounds__(256) void count_kernel(const int* __restrict__ dst) {
    int i = blockIdx.x * blockDim.x + threadIdx.x;
    if (i >= REDGES) return;
    int r = i / E;
    atomicAdd(&g_cnti[r * N_NODES + dst[i]], 1);
}

// scan1 + scan2 fused: per-block exclusive scan; last block scans block sums.
__global__ __launch_bounds__(512) void scan12_kernel() {
    __shared__ int tmp[512];
    __shared__ int sdata[NB];
    __shared__ int islast;
    int t = threadIdx.x, lane = t & 31;
    int i = blockIdx.x * 512 + t;
    int v = (i < RN) ? g_cnti[i] : 0;
    tmp[t] = v;
    __syncthreads();
    for (int o = 1; o < 512; o <<= 1) {
        int a = (t >= o) ? tmp[t - o] : 0;
        __syncthreads();
        tmp[t] += a;
        __syncthreads();
    }
    if (i < RN) g_off[i] = tmp[t] - v;
    if (t == 511) {
        g_bsum[blockIdx.x] = tmp[511];
        __threadfence();
        int prev = atomicAdd(&g_scan_ctr, 1);
        islast = (prev == NB - 1);
    }
    __syncthreads();
    if (!islast) return;
    __threadfence();
    for (int j = t; j < NB; j += 512) sdata[j] = g_bsum[j];
    __syncthreads();
    if (t < 32) {
        // lane handles 25 contiguous entries (32*25 = 800 >= 782)
        int start = lane * 25;
        int sum = 0;
        #pragma unroll 1
        for (int j = 0; j < 25; j++) {
            int idx = start + j;
            if (idx < NB) { int x = sdata[idx]; sdata[idx] = sum; sum += x; }
        }
        int vv = sum;
        #pragma unroll
        for (int o = 1; o < 32; o <<= 1) {
            int n = __shfl_up_sync(0xffffffffu, vv, o);
            if (lane >= o) vv += n;
        }
        int excl = vv - sum;
        #pragma unroll 1
        for (int j = 0; j < 25; j++) {
            int idx = start + j;
            if (idx < NB) g_bscan[idx] = sdata[idx] + excl;
        }
    }
}

// global position = local offset + g_bscan[rd>>9]; fill bumps g_off to local END
__global__ __launch_bounds__(256) void fill_kernel(const int* __restrict__ src,
                                                   const int* __restrict__ dst) {
    int i = blockIdx.x * blockDim.x + threadIdx.x;
    if (i >= REDGES) return;
    int r = i / E;
    int rd = r * N_NODES + dst[i];
    int pos = atomicAdd(&g_off[rd], 1) + g_bscan[rd >> 9];
    g_esrc[pos] = src[i];
}

// ---------------- aggregate: warp per node, loop relations (R4 v1) -------------
__global__ __launch_bounds__(256) void aggregate_kernel(const float* __restrict__ x) {
    int w = (int)(((size_t)blockIdx.x * blockDim.x + threadIdx.x) >> 5);
    int lane = threadIdx.x & 31;
    if (w >= N_NODES) return;

    #pragma unroll
    for (int r = 0; r < R; r++) {
        int rd = r * N_NODES + w;
        int cdeg = g_cnti[rd];
        int base = g_off[rd] + g_bscan[rd >> 9] - cdeg;   // global base
        float4 s0 = make_float4(0.f, 0.f, 0.f, 0.f);
        float4 s1 = make_float4(0.f, 0.f, 0.f, 0.f);
        int e = 0;
        for (; e + 2 <= cdeg; e += 2) {
            int sa = g_esrc[base + e];
            int sb = g_esrc[base + e + 1];
            float4 va = *(const float4*)(x + (size_t)sa * D + lane * 4);
            float4 vb = *(const float4*)(x + (size_t)sb * D + lane * 4);
            s0.x += va.x; s0.y += va.y; s0.z += va.z; s0.w += va.w;
            s1.x += vb.x; s1.y += vb.y; s1.z += vb.z; s1.w += vb.w;
        }
        if (e < cdeg) {
            int sa = g_esrc[base + e];
            float4 va = *(const float4*)(x + (size_t)sa * D + lane * 4);
            s0.x += va.x; s0.y += va.y; s0.z += va.z; s0.w += va.w;
        }
        float ic = 1.f / fmaxf((float)cdeg, 1.f);
        float4 o;
        o.x = (s0.x + s1.x) * ic;
        o.y = (s0.y + s1.y) * ic;
        o.z = (s0.z + s1.z) * ic;
        o.w = (s0.w + s1.w) * ic;
        *(float4*)(g_neigh + (size_t)rd * D + lane * 4) = o;
    }
}

// ---------------- tf32 mma.sync GEMM (R4 verbatim) -----------------------------
// Block tile 128x128, 128 threads = 4 warps in 2x2, warp tile 64x64.
__global__ __launch_bounds__(128) void gemm_kernel(const float* __restrict__ x,
                                                   float* __restrict__ out) {
    __shared__ uint32_t As[32][136];
    __shared__ uint32_t Bs[32][136];

    int tid  = threadIdx.x;
    int wid  = tid >> 5, lane = tid & 31;
    int qid  = lane >> 2, kid = lane & 3;
    int wm   = wid & 1, wn = wid >> 1;
    int row0 = blockIdx.x * 128;

    float c[4][8][4];
    #pragma unroll
    for (int mt = 0; mt < 4; mt++)
        #pragma unroll
        for (int nt = 0; nt < 8; nt++)
            #pragma unroll
            for (int j = 0; j < 4; j++) c[mt][nt][j] = 0.f;

    #pragma unroll 1
    for (int seg = 0; seg < R + 1; seg++) {
        const float* Asrc = (seg == 0) ? x : (g_neigh + (size_t)(seg - 1) * N_NODES * D);
        const float* Bsrc = g_Wt + seg * D * D;

        #pragma unroll 1
        for (int k0 = 0; k0 < D; k0 += 32) {
            __syncthreads();
            // ---- A chunk: 128 rows x 32 k -> transposed+swizzled ----
            #pragma unroll
            for (int p = 0; p < 8; p++) {
                int q = tid + p * 128;
                int row = q >> 3, kq = q & 7;
                int n = row0 + row;
                float4 v = make_float4(0.f, 0.f, 0.f, 0.f);
                if (n < N_NODES) v = *(const float4*)(Asrc + (size_t)n * D + k0 + kq * 4);
                #pragma unroll
                for (int i = 0; i < 4; i++) {
                    int k = kq * 4 + i;
                    float f = (i == 0) ? v.x : (i == 1) ? v.y : (i == 2) ? v.z : v.w;
                    As[k][row ^ (((k >> 2) & 3) << 3)] = f2tf32(f);
                }
            }
            // ---- B chunk: 32 k-rows x 128 n ----
            #pragma unroll
            for (int p = 0; p < 8; p++) {
                int q = tid + p * 128;
                int kk = q >> 5, nq = q & 31;
                float4 v = *(const float4*)(Bsrc + (size_t)(k0 + kk) * D + nq * 4);
                uint4 u;
                u.x = f2tf32(v.x); u.y = f2tf32(v.y); u.z = f2tf32(v.z); u.w = f2tf32(v.w);
                *(uint4*)&Bs[kk][nq * 4] = u;
            }
            __syncthreads();
            // ---- 4 k8-steps ----
            #pragma unroll
            for (int kk8 = 0; kk8 < 4; kk8++) {
                int k8 = kk8 * 8;
                int C0 = ((2 * kk8) & 3) << 3;
                int C1 = ((2 * kk8 + 1) & 3) << 3;
                uint32_t a[4][4], b[8][2];
                #pragma unroll
                for (int mt = 0; mt < 4; mt++) {
                    int row = wm * 64 + mt * 16 + qid;
                    a[mt][0] = As[k8 + kid][row ^ C0];
                    a[mt][1] = As[k8 + kid][(row + 8) ^ C0];
                    a[mt][2] = As[k8 + 4 + kid][row ^ C1];
                    a[mt][3] = As[k8 + 4 + kid][(row + 8) ^ C1];
                }
                #pragma unroll
                for (int nt = 0; nt < 8; nt++) {
                    int col = wn * 64 + nt * 8 + qid;
                    b[nt][0] = Bs[k8 + kid][col];
                    b[nt][1] = Bs[k8 + 4 + kid][col];
                }
                #pragma unroll
                for (int mt = 0; mt < 4; mt++)
                    #pragma unroll
                    for (int nt = 0; nt < 8; nt++)
                        mma8(c[mt][nt], a[mt], b[nt]);
            }
        }
    }

    // ---- epilogue: add mean bias, store float2 pairs ----
    #pragma unroll
    for (int mt = 0; mt < 4; mt++) {
        int r0q = row0 + wm * 64 + mt * 16 + qid;
        #pragma unroll
        for (int nt = 0; nt < 8; nt++) {
            int col = wn * 64 + nt * 8 + kid * 2;
            float b0 = g_bavg[col], b1 = g_bavg[col + 1];
            if (r0q < N_NODES) {
                float2 o = make_float2(c[mt][nt][0] + b0, c[mt][nt][1] + b1);
                *(float2*)(out + (size_t)r0q * D + col) = o;
            }
            if (r0q + 8 < N_NODES) {
                float2 o = make_float2(c[mt][nt][2] + b0, c[mt][nt][3] + b1);
                *(float2*)(out + (size_t)(r0q + 8) * D + col) = o;
            }
        }
    }
}

// ---------------- launch --------------------------------------------------------
extern "C" void kernel_launch(void* const* d_in, const int* in_sizes, int n_in,
                              void* d_out, int out_size) {
    const float* x      = (const float*)d_in[0];
    const int*   src    = (const int*)d_in[1];
    const int*   dst    = (const int*)d_in[2];
    const float* Wself  = (const float*)d_in[3];
    const float* Wneigh = (const float*)d_in[4];
    const float* b      = (const float*)d_in[5];
    float* out = (float*)d_out;

    zc_kernel<<<(RN + 255) / 256, 256>>>(Wself, Wneigh, b);       // 0
    count_kernel<<<(REDGES + 255) / 256, 256>>>(dst);             // 1
    scan12_kernel<<<NB, 512>>>();                                 // 2
    fill_kernel<<<(REDGES + 255) / 256, 256>>>(src, dst);         // 3 <- profiled
    aggregate_kernel<<<(N_NODES * 32 + 255) / 256, 256>>>(x);     // 4
    gemm_kernel<<<NTILE, 128>>>(x, out);                          // 5
    (void)in_sizes; (void)n_in; (void)out_size;
}